// round 15
// baseline (speedup 1.0000x reference)
#include <cuda_runtime.h>
#include <cstdint>

#define D 128
#define NGRAPH 64
#define MAXN 50176
#define MAXE 1600000

// ---------------- scratch (device globals; no allocation allowed) ----------------
__device__ float g_xwp[(size_t)MAXN * D];
__device__ float g_xwn[(size_t)MAXN * D];
__device__ float g_h0[(size_t)MAXN * D];
__device__ float g_h1[(size_t)MAXN * D];
__device__ float g_degp[MAXN];   // deg -> dinv (in place)
__device__ float g_degn[MAXN];
__device__ int   g_cnt[MAXN];
__device__ int   g_rowptr[MAXN + 1];
__device__ int   g_cursor[MAXN];
__device__ int   g_col[MAXE];
__device__ float g_val[MAXE];
__device__ int   g_start[NGRAPH];
__device__ int   g_end[NGRAPH];
__device__ int   g_is64;         // 1 if index buffers are int64, 0 if int32

// ---------------- dtype detection: int64 buffers have zero hi-words ----------------
__global__ void detect_kernel(const int* __restrict__ ei32, int nelem) {
    if (threadIdx.x == 0 && blockIdx.x == 0) {
        int is64 = 1;
        int cnt = 64;
        if (nelem / 2 < cnt) cnt = nelem / 2;
        for (int i = 0; i < cnt; i++) {
            if (ei32[2 * i + 1] != 0) { is64 = 0; break; }
        }
        g_is64 = is64;
    }
}

__device__ __forceinline__ int load_idx(const void* p, size_t i, int is64) {
    return is64 ? (int)((const long long*)p)[i] : ((const int*)p)[i];
}

// ---------------- init ----------------
__global__ void init_kernel(int n) {
    int i = blockIdx.x * blockDim.x + threadIdx.x;
    if (i < n) {
        g_degp[i] = 1.0f;   // +1 self-loop contribution to degree
        g_degn[i] = 1.0f;
        g_cnt[i] = 0;
    }
    if (i < NGRAPH) { g_start[i] = 0; g_end[i] = 0; }
}

// ---------------- edge pass 1: degrees + histogram ----------------
__global__ void edge_deg_kernel(const void* __restrict__ ei,
                                const float* __restrict__ ew, int E, int n) {
    int e = blockIdx.x * blockDim.x + threadIdx.x;
    if (e >= E) return;
    const int is64 = g_is64;
    int dst = load_idx(ei, (size_t)E + e, is64);
    if ((unsigned)dst >= (unsigned)n) return;   // defensive: never trap
    float w = ew[e];
    if (w > 0.f)      atomicAdd(&g_degp[dst], w);
    else if (w < 0.f) atomicAdd(&g_degn[dst], -w);
    atomicAdd(&g_cnt[dst], 1);
}

// ---------------- deg -> dinv ----------------
__global__ void dinv_kernel(int n) {
    int i = blockIdx.x * blockDim.x + threadIdx.x;
    if (i >= n) return;
    g_degp[i] = rsqrtf(g_degp[i]);
    g_degn[i] = rsqrtf(g_degn[i]);
}

// ---------------- exclusive scan of g_cnt -> g_rowptr, g_cursor (single block) ----
__global__ void scan_kernel(int n) {
    __shared__ int sm[1024];
    __shared__ int carry;
    int t = threadIdx.x;
    if (t == 0) carry = 0;
    __syncthreads();
    for (int base = 0; base < n; base += 1024) {
        int i = base + t;
        int v = (i < n) ? g_cnt[i] : 0;
        sm[t] = v;
        __syncthreads();
        #pragma unroll
        for (int off = 1; off < 1024; off <<= 1) {
            int u = (t >= off) ? sm[t - off] : 0;
            __syncthreads();
            sm[t] += u;
            __syncthreads();
        }
        int excl = sm[t] - v + carry;
        if (i < n) { g_rowptr[i] = excl; g_cursor[i] = excl; }
        __syncthreads();
        if (t == 1023) carry += sm[1023];
        __syncthreads();
    }
    if (t == 0) g_rowptr[n] = carry;
}

// ---------------- edge pass 2: fill CSR (signed norm encodes branch) ----------------
__global__ void edge_fill_kernel(const void* __restrict__ ei,
                                 const float* __restrict__ ew, int E, int n) {
    int e = blockIdx.x * blockDim.x + threadIdx.x;
    if (e >= E) return;
    const int is64 = g_is64;
    int s = load_idx(ei, e, is64);
    int d = load_idx(ei, (size_t)E + e, is64);
    if ((unsigned)s >= (unsigned)n || (unsigned)d >= (unsigned)n) return;
    float w = ew[e];
    float v;
    if (w > 0.f)      v = g_degp[s] * w * g_degp[d];          // >0 : pos branch
    else if (w < 0.f) v = g_degn[s] * w * g_degn[d];          // <0 : neg branch
    else              v = 0.f;
    int p = atomicAdd(&g_cursor[d], 1);
    if ((unsigned)p < (unsigned)E) { g_col[p] = s; g_val[p] = v; }
}

// ---------------- dual GEMM: out = A @ W  (branch by blockIdx.y) ----------------
// src_sel: 0 = external pointer A, 1 = g_h0, 2 = g_h1
__global__ __launch_bounds__(256) void gemm_dual_kernel(
        const float* __restrict__ Aext, int src_sel,
        const float* __restrict__ Wp, const float* __restrict__ Wn, int n) {
    const float* A = (src_sel == 0) ? Aext : (src_sel == 1 ? g_h0 : g_h1);
    const float* W = (blockIdx.y == 0) ? Wp : Wn;
    float* out = (blockIdx.y == 0) ? g_xwp : g_xwn;
    const int row0 = blockIdx.x * 128;
    __shared__ float As[16][128];
    __shared__ float Bs[16][128];
    const int tid = threadIdx.x;
    const int ty = tid >> 4, tx = tid & 15;
    float acc[8][8];
    #pragma unroll
    for (int i = 0; i < 8; i++)
        #pragma unroll
        for (int j = 0; j < 8; j++) acc[i][j] = 0.f;

    for (int k0 = 0; k0 < 128; k0 += 16) {
        #pragma unroll
        for (int i = 0; i < 2; i++) {
            int v = tid * 2 + i;           // 0..511
            int r = v >> 2, kq = v & 3;
            float4 a = make_float4(0.f, 0.f, 0.f, 0.f);
            if (row0 + r < n)
                a = reinterpret_cast<const float4*>(A + (size_t)(row0 + r) * D + k0)[kq];
            As[kq * 4 + 0][r] = a.x; As[kq * 4 + 1][r] = a.y;
            As[kq * 4 + 2][r] = a.z; As[kq * 4 + 3][r] = a.w;
        }
        #pragma unroll
        for (int i = 0; i < 2; i++) {
            int v = tid * 2 + i;
            int r = v >> 5, c = v & 31;
            float4 b = reinterpret_cast<const float4*>(W + (size_t)(k0 + r) * D)[c];
            *reinterpret_cast<float4*>(&Bs[r][c * 4]) = b;
        }
        __syncthreads();
        #pragma unroll
        for (int k = 0; k < 16; k++) {
            float ra[8], rb[8];
            *(float4*)&ra[0] = *(float4*)&As[k][ty * 8];
            *(float4*)&ra[4] = *(float4*)&As[k][ty * 8 + 4];
            *(float4*)&rb[0] = *(float4*)&Bs[k][tx * 8];
            *(float4*)&rb[4] = *(float4*)&Bs[k][tx * 8 + 4];
            #pragma unroll
            for (int i = 0; i < 8; i++)
                #pragma unroll
                for (int j = 0; j < 8; j++)
                    acc[i][j] = fmaf(ra[i], rb[j], acc[i][j]);
        }
        __syncthreads();
    }
    #pragma unroll
    for (int i = 0; i < 8; i++) {
        int r = row0 + ty * 8 + i;
        if (r < n) {
            float4 o0 = make_float4(acc[i][0], acc[i][1], acc[i][2], acc[i][3]);
            float4 o1 = make_float4(acc[i][4], acc[i][5], acc[i][6], acc[i][7]);
            float4* dst = reinterpret_cast<float4*>(out + (size_t)r * D + tx * 8);
            dst[0] = o0; dst[1] = o1;
        }
    }
}

// ---------------- aggregation (gather, no atomics) + bias + relu-combine --------
// dst_sel: 0 = g_h0, 1 = g_h1
__global__ __launch_bounds__(128) void agg_kernel(
        const float* __restrict__ bp, const float* __restrict__ bn,
        int dst_sel) {
    float* hout = (dst_sel == 0) ? g_h0 : g_h1;
    const int node = blockIdx.x;
    const int f = threadIdx.x;
    __shared__ int   scol[128];
    __shared__ float sval[128];
    const int beg = g_rowptr[node], end = g_rowptr[node + 1];
    float accp = 0.f, accn = 0.f;
    for (int base = beg; base < end; base += 128) {
        int idx = base + f;
        if (idx < end) { scol[f] = g_col[idx]; sval[f] = g_val[idx]; }
        __syncthreads();
        int cnt = min(128, end - base);
        for (int j = 0; j < cnt; j++) {
            float c = sval[j];
            int s = scol[j];
            if (c > 0.f)      accp += c * g_xwp[(size_t)s * D + f];
            else if (c < 0.f) accn += (-c) * g_xwn[(size_t)s * D + f];
        }
        __syncthreads();
    }
    float dp = g_degp[node], dn = g_degn[node];
    accp += dp * dp * g_xwp[(size_t)node * D + f] + bp[f];
    accn += dn * dn * g_xwn[(size_t)node * D + f] + bn[f];
    hout[(size_t)node * D + f] = fmaxf(accp, 0.f) - fmaxf(accn, 0.f);
}

// ---------------- graph boundaries from sorted batch ----------------
__global__ void bounds_kernel(const void* __restrict__ batch, int n) {
    int i = blockIdx.x * blockDim.x + threadIdx.x;
    if (i >= n) return;
    const int is64 = g_is64;
    int b = load_idx(batch, i, is64);
    if ((unsigned)b >= (unsigned)NGRAPH) return;
    if (i == 0) g_start[b] = 0;
    else {
        int pb = load_idx(batch, i - 1, is64);
        if ((unsigned)pb < (unsigned)NGRAPH && pb != b) { g_start[b] = i; g_end[pb] = i; }
    }
    if (i == n - 1) g_end[b] = n;
}

// ---------------- pooled mean + LayerNorm (one block per graph; reads g_h0) ------
__global__ __launch_bounds__(128) void pool_ln_kernel(
        const float* __restrict__ gamma, const float* __restrict__ beta,
        float* __restrict__ out) {
    const int g = blockIdx.x;
    const int f = threadIdx.x;
    const int s = g_start[g], e = g_end[g];
    float sum = 0.f;
    for (int i = s; i < e; i++) sum += g_h0[(size_t)i * D + f];
    float cnt = (float)(e - s);
    float pooled = sum / fmaxf(cnt, 1.f);
    __shared__ float red[128];
    red[f] = pooled;
    __syncthreads();
    #pragma unroll
    for (int off = 64; off > 0; off >>= 1) {
        if (f < off) red[f] += red[f + off];
        __syncthreads();
    }
    float mu = red[0] * (1.f / 128.f);
    __syncthreads();
    float d = pooled - mu;
    red[f] = d * d;
    __syncthreads();
    #pragma unroll
    for (int off = 64; off > 0; off >>= 1) {
        if (f < off) red[f] += red[f + off];
        __syncthreads();
    }
    float var = red[0] * (1.f / 128.f);
    out[g * D + f] = d * rsqrtf(var + 1e-5f) * gamma[f] + beta[f];
}

// ---------------- launch: self-identifying input binding ----------------
extern "C" void kernel_launch(void* const* d_in, const int* in_sizes, int n_in,
                              void* d_out, int out_size) {
    // Rank inputs by size, stable on ties (preserves original relative order).
    // Size classes: x (N*D) > edge_index (2E) > edge_weight (E) > batch (N)
    //               > W pair (L*D*D) x2 > b pair (L*D) x2 > ln pair (D) x2
    int order[16];
    int m = (n_in < 16) ? n_in : 16;
    for (int i = 0; i < m; i++) order[i] = i;
    for (int i = 0; i < m; i++) {          // stable selection sort, descending size
        int best = i;
        for (int j = i + 1; j < m; j++)
            if (in_sizes[order[j]] > in_sizes[order[best]]) best = j;
        int t = order[i]; order[i] = order[best]; order[best] = t;
    }
    const int xi  = order[0];   // x           : N*D
    const int eii = order[1];   // edge_index  : 2E
    const int ewi = order[2];   // edge_weight : E
    const int bti = order[3];   // batch       : N
    const int wA  = order[4], wB = order[5];   // W pair
    const int bA  = order[6], bB = order[7];   // b pair
    const int lA  = order[8], lB = order[9];   // ln pair
    // Scheme detection: dict order puts x first; alphabetical puts W_neg first.
    const bool dict_order = (xi == 0);
    const int wPos = dict_order ? wA : wB;   // dict: pos before neg; alpha: neg first
    const int wNeg = dict_order ? wB : wA;
    const int bPos = dict_order ? bA : bB;
    const int bNeg = dict_order ? bB : bA;
    const int gI   = dict_order ? lA : lB;   // dict: gamma before beta; alpha: beta first
    const int bI   = dict_order ? lB : lA;

    const float* x     = (const float*)d_in[xi];
    const void*  ei    = d_in[eii];            // int32 or int64, detected on device
    const float* ew    = (const float*)d_in[ewi];
    const void*  batch = d_in[bti];
    const float* W_pos = (const float*)d_in[wPos];
    const float* b_pos = (const float*)d_in[bPos];
    const float* W_neg = (const float*)d_in[wNeg];
    const float* b_neg = (const float*)d_in[bNeg];
    const float* gamma = (const float*)d_in[gI];
    const float* beta  = (const float*)d_in[bI];
    float* out = (float*)d_out;

    int N = in_sizes[xi] / D;
    int E = in_sizes[ewi];
    if (N > MAXN) N = MAXN;
    if (E > MAXE) E = MAXE;

    const int TB = 256;
    detect_kernel<<<1, 32>>>((const int*)ei, in_sizes[eii]);
    init_kernel<<<(N + TB - 1) / TB, TB>>>(N);
    edge_deg_kernel<<<(E + TB - 1) / TB, TB>>>(ei, ew, E, N);
    dinv_kernel<<<(N + TB - 1) / TB, TB>>>(N);
    scan_kernel<<<1, 1024>>>(N);
    edge_fill_kernel<<<(E + TB - 1) / TB, TB>>>(ei, ew, E, N);
    bounds_kernel<<<(N + TB - 1) / TB, TB>>>(batch, N);

    const int rowTiles = (N + 127) / 128;
    // layer 0: x -> h0 ; layer 1: h0 -> h1 ; layer 2: h1 -> h0
    const int src_sels[3] = { 0, 1, 2 };
    const int dst_sels[3] = { 0, 1, 0 };
    for (int l = 0; l < 3; l++) {
        gemm_dual_kernel<<<dim3(rowTiles, 2), 256>>>(x, src_sels[l],
                                                     W_pos + (size_t)l * D * D,
                                                     W_neg + (size_t)l * D * D, N);
        agg_kernel<<<N, 128>>>(b_pos + (size_t)l * D, b_neg + (size_t)l * D, dst_sels[l]);
    }
    pool_ln_kernel<<<NGRAPH, 128>>>(gamma, beta, out);
}

// round 17
// speedup vs baseline: 1.6608x; 1.6608x over previous
#include <cuda_runtime.h>
#include <cstdint>

#define D 128
#define NGRAPH 64
#define MAXN 50176
#define MAXE 1600000

// ---------------- scratch (device globals; no allocation allowed) ----------------
__device__ float g_xwp[(size_t)MAXN * D];
__device__ float g_xwn[(size_t)MAXN * D];
__device__ float g_h0[(size_t)MAXN * D];
__device__ float g_h1[(size_t)MAXN * D];
__device__ float g_degp[MAXN];   // deg -> dinv (in place)
__device__ float g_degn[MAXN];
__device__ int   g_cnt[MAXN];
__device__ int   g_rowptr[MAXN + 1];
__device__ int   g_cursor[MAXN];    // pos cursor (fills forward); final = end of pos region
__device__ int   g_cursor2[MAXN];   // neg cursor (fills backward); final = start-1 of neg region
__device__ int   g_col[MAXE];
__device__ float g_val[MAXE];
__device__ int   g_bsum[512];
__device__ int   g_boff[512];
__device__ int   g_start[NGRAPH];
__device__ int   g_end[NGRAPH];
__device__ int   g_is64;         // 1 if index buffers are int64, 0 if int32

// ---------------- dtype detection: int64 buffers have zero hi-words ----------------
__global__ void detect_kernel(const int* __restrict__ ei32, int nelem) {
    if (threadIdx.x == 0 && blockIdx.x == 0) {
        int is64 = 1;
        int cnt = 64;
        if (nelem / 2 < cnt) cnt = nelem / 2;
        for (int i = 0; i < cnt; i++) {
            if (ei32[2 * i + 1] != 0) { is64 = 0; break; }
        }
        g_is64 = is64;
    }
}

__device__ __forceinline__ int load_idx(const void* p, size_t i, int is64) {
    return is64 ? (int)((const long long*)p)[i] : ((const int*)p)[i];
}

// ---------------- init ----------------
__global__ void init_kernel(int n) {
    int i = blockIdx.x * blockDim.x + threadIdx.x;
    if (i < n) {
        g_degp[i] = 1.0f;   // +1 self-loop contribution to degree
        g_degn[i] = 1.0f;
        g_cnt[i] = 0;
    }
    if (i < NGRAPH) { g_start[i] = 0; g_end[i] = 0; }
}

// ---------------- edge pass 1: degrees + histogram ----------------
__global__ void edge_deg_kernel(const void* __restrict__ ei,
                                const float* __restrict__ ew, int E, int n) {
    int e = blockIdx.x * blockDim.x + threadIdx.x;
    if (e >= E) return;
    const int is64 = g_is64;
    int dst = load_idx(ei, (size_t)E + e, is64);
    if ((unsigned)dst >= (unsigned)n) return;   // defensive: never trap
    float w = ew[e];
    if (w > 0.f)      atomicAdd(&g_degp[dst], w);
    else if (w < 0.f) atomicAdd(&g_degn[dst], -w);
    atomicAdd(&g_cnt[dst], 1);
}

// ---------------- deg -> dinv ----------------
__global__ void dinv_kernel(int n) {
    int i = blockIdx.x * blockDim.x + threadIdx.x;
    if (i >= n) return;
    g_degp[i] = rsqrtf(g_degp[i]);
    g_degn[i] = rsqrtf(g_degn[i]);
}

// ---------------- decoupled scan: A (per-block), B (block sums), C (apply) ------
__device__ __forceinline__ int warp_incl_scan(int v) {
    #pragma unroll
    for (int o = 1; o < 32; o <<= 1) {
        int u = __shfl_up_sync(0xffffffffu, v, o);
        if ((threadIdx.x & 31) >= o) v += u;
    }
    return v;
}

__global__ __launch_bounds__(256) void scanA_kernel(int n) {
    int t = threadIdx.x, b = blockIdx.x, i = b * 256 + t;
    int v = (i < n) ? g_cnt[i] : 0;
    int incl = warp_incl_scan(v);
    __shared__ int ws[8];
    int w = t >> 5, l = t & 31;
    if (l == 31) ws[w] = incl;
    __syncthreads();
    if (t == 0) {
        int s = 0;
        #pragma unroll
        for (int k = 0; k < 8; k++) { int x = ws[k]; ws[k] = s; s += x; }
    }
    __syncthreads();
    int excl = incl - v + ws[w];
    if (i < n) g_rowptr[i] = excl;           // local (pre-offset)
    if (t == 255) g_bsum[b] = excl + v;      // block total
}

__global__ __launch_bounds__(256) void scanB_kernel(int nb) {
    int t = threadIdx.x;
    int v = (t < nb) ? g_bsum[t] : 0;
    int incl = warp_incl_scan(v);
    __shared__ int ws[8];
    int w = t >> 5, l = t & 31;
    if (l == 31) ws[w] = incl;
    __syncthreads();
    if (t == 0) {
        int s = 0;
        #pragma unroll
        for (int k = 0; k < 8; k++) { int x = ws[k]; ws[k] = s; s += x; }
    }
    __syncthreads();
    g_boff[t] = incl - v + ws[w];
}

__global__ __launch_bounds__(256) void scanC_kernel(int n) {
    int i = blockIdx.x * blockDim.x + threadIdx.x;
    if (i >= n) return;
    int rp = g_rowptr[i] + g_boff[i >> 8];
    int incl = rp + g_cnt[i];
    g_rowptr[i] = rp;
    g_cursor[i] = rp;            // pos fills forward from row start
    g_cursor2[i] = incl - 1;     // neg fills backward from row end
    if (i == n - 1) g_rowptr[n] = incl;
}

// ---------------- edge pass 2: fill sign-partitioned CSR ----------------
// pos edges at row front (norm > 0), neg edges at row back (stored norm > 0).
__global__ void edge_fill_kernel(const void* __restrict__ ei,
                                 const float* __restrict__ ew, int E, int n) {
    int e = blockIdx.x * blockDim.x + threadIdx.x;
    if (e >= E) return;
    const int is64 = g_is64;
    int s = load_idx(ei, e, is64);
    int d = load_idx(ei, (size_t)E + e, is64);
    if ((unsigned)s >= (unsigned)n || (unsigned)d >= (unsigned)n) return;
    float w = ew[e];
    if (w > 0.f) {
        float v = g_degp[s] * w * g_degp[d];
        int p = atomicAdd(&g_cursor[d], 1);
        if ((unsigned)p < (unsigned)E) { g_col[p] = s; g_val[p] = v; }
    } else if (w < 0.f) {
        float v = g_degn[s] * (-w) * g_degn[d];
        int p = atomicAdd(&g_cursor2[d], -1);
        if ((unsigned)p < (unsigned)E) { g_col[p] = s; g_val[p] = v; }
    }
    // w == 0: skipped entirely (gap in the middle of the row, never read)
}

// ---------------- dual GEMM: out = A @ W  (branch by blockIdx.y) ----------------
// src_sel: 0 = external pointer A, 1 = g_h0, 2 = g_h1
__global__ __launch_bounds__(256) void gemm_dual_kernel(
        const float* __restrict__ Aext, int src_sel,
        const float* __restrict__ Wp, const float* __restrict__ Wn, int n) {
    const float* A = (src_sel == 0) ? Aext : (src_sel == 1 ? g_h0 : g_h1);
    const float* W = (blockIdx.y == 0) ? Wp : Wn;
    float* out = (blockIdx.y == 0) ? g_xwp : g_xwn;
    const int row0 = blockIdx.x * 128;
    __shared__ float As[16][128];
    __shared__ float Bs[16][128];
    const int tid = threadIdx.x;
    const int ty = tid >> 4, tx = tid & 15;
    float acc[8][8];
    #pragma unroll
    for (int i = 0; i < 8; i++)
        #pragma unroll
        for (int j = 0; j < 8; j++) acc[i][j] = 0.f;

    for (int k0 = 0; k0 < 128; k0 += 16) {
        #pragma unroll
        for (int i = 0; i < 2; i++) {
            int v = tid * 2 + i;           // 0..511
            int r = v >> 2, kq = v & 3;
            float4 a = make_float4(0.f, 0.f, 0.f, 0.f);
            if (row0 + r < n)
                a = reinterpret_cast<const float4*>(A + (size_t)(row0 + r) * D + k0)[kq];
            As[kq * 4 + 0][r] = a.x; As[kq * 4 + 1][r] = a.y;
            As[kq * 4 + 2][r] = a.z; As[kq * 4 + 3][r] = a.w;
        }
        #pragma unroll
        for (int i = 0; i < 2; i++) {
            int v = tid * 2 + i;
            int r = v >> 5, c = v & 31;
            float4 b = reinterpret_cast<const float4*>(W + (size_t)(k0 + r) * D)[c];
            *reinterpret_cast<float4*>(&Bs[r][c * 4]) = b;
        }
        __syncthreads();
        #pragma unroll
        for (int k = 0; k < 16; k++) {
            float ra[8], rb[8];
            *(float4*)&ra[0] = *(float4*)&As[k][ty * 8];
            *(float4*)&ra[4] = *(float4*)&As[k][ty * 8 + 4];
            *(float4*)&rb[0] = *(float4*)&Bs[k][tx * 8];
            *(float4*)&rb[4] = *(float4*)&Bs[k][tx * 8 + 4];
            #pragma unroll
            for (int i = 0; i < 8; i++)
                #pragma unroll
                for (int j = 0; j < 8; j++)
                    acc[i][j] = fmaf(ra[i], rb[j], acc[i][j]);
        }
        __syncthreads();
    }
    #pragma unroll
    for (int i = 0; i < 8; i++) {
        int r = row0 + ty * 8 + i;
        if (r < n) {
            float4 o0 = make_float4(acc[i][0], acc[i][1], acc[i][2], acc[i][3]);
            float4 o1 = make_float4(acc[i][4], acc[i][5], acc[i][6], acc[i][7]);
            float4* dst = reinterpret_cast<float4*>(out + (size_t)r * D + tx * 8);
            dst[0] = o0; dst[1] = o1;
        }
    }
}

// ---------------- aggregation: vectorized gather, 4 edges in flight -------------
// 4 warps per node; warp w takes edges w, w+4, ...; lane l covers features [4l,4l+4)
// dst_sel: 0 = g_h0, 1 = g_h1
__global__ __launch_bounds__(128) void agg_kernel(
        const float* __restrict__ bp, const float* __restrict__ bn,
        int dst_sel) {
    float* hout = (dst_sel == 0) ? g_h0 : g_h1;
    const int node = blockIdx.x;
    const int t = threadIdx.x, w = t >> 5, l = t & 31;
    const int beg  = g_rowptr[node];
    const int cpos = g_cursor[node];      // end of pos region (final cursor)
    const int cneg = g_cursor2[node];     // neg region = (cneg, end)
    const int end  = g_rowptr[node + 1];
    const float4* XP = (const float4*)g_xwp;
    const float4* XN = (const float4*)g_xwn;
    float4 ap = make_float4(0.f, 0.f, 0.f, 0.f);
    float4 an = make_float4(0.f, 0.f, 0.f, 0.f);

    #pragma unroll 2
    for (int idx = beg + w; idx < cpos; idx += 4) {
        int s = g_col[idx];
        float c = g_val[idx];
        float4 v = XP[(size_t)s * 32 + l];
        ap.x += c * v.x; ap.y += c * v.y; ap.z += c * v.z; ap.w += c * v.w;
    }
    #pragma unroll 2
    for (int idx = cneg + 1 + w; idx < end; idx += 4) {
        int s = g_col[idx];
        float c = g_val[idx];
        float4 v = XN[(size_t)s * 32 + l];
        an.x += c * v.x; an.y += c * v.y; an.z += c * v.z; an.w += c * v.w;
    }

    __shared__ float sp[4 * 128];
    __shared__ float sn[4 * 128];
    ((float4*)sp)[w * 32 + l] = ap;
    ((float4*)sn)[w * 32 + l] = an;
    __syncthreads();

    const int f = t;
    float accp = sp[f] + sp[128 + f] + sp[256 + f] + sp[384 + f];
    float accn = sn[f] + sn[128 + f] + sn[256 + f] + sn[384 + f];
    float dp = g_degp[node], dn = g_degn[node];
    accp += dp * dp * g_xwp[(size_t)node * D + f] + bp[f];
    accn += dn * dn * g_xwn[(size_t)node * D + f] + bn[f];
    hout[(size_t)node * D + f] = fmaxf(accp, 0.f) - fmaxf(accn, 0.f);
}

// ---------------- graph boundaries from sorted batch ----------------
__global__ void bounds_kernel(const void* __restrict__ batch, int n) {
    int i = blockIdx.x * blockDim.x + threadIdx.x;
    if (i >= n) return;
    const int is64 = g_is64;
    int b = load_idx(batch, i, is64);
    if ((unsigned)b >= (unsigned)NGRAPH) return;
    if (i == 0) g_start[b] = 0;
    else {
        int pb = load_idx(batch, i - 1, is64);
        if ((unsigned)pb < (unsigned)NGRAPH && pb != b) { g_start[b] = i; g_end[pb] = i; }
    }
    if (i == n - 1) g_end[b] = n;
}

// ---------------- pooled mean + LayerNorm (one block per graph; reads g_h0) ------
// 256 threads: 8 row-groups x 32 lanes (float4) for the sum, then 128-thread LN.
__global__ __launch_bounds__(256) void pool_ln_kernel(
        const float* __restrict__ gamma, const float* __restrict__ beta,
        float* __restrict__ out) {
    const int g = blockIdx.x;
    const int t = threadIdx.x, rg = t >> 5, l = t & 31;
    const int s = g_start[g], e = g_end[g];
    const float4* H = (const float4*)g_h0;
    float4 acc = make_float4(0.f, 0.f, 0.f, 0.f);
    for (int i = s + rg; i < e; i += 8) {
        float4 v = H[(size_t)i * 32 + l];
        acc.x += v.x; acc.y += v.y; acc.z += v.z; acc.w += v.w;
    }
    __shared__ float sred[8 * 128];
    ((float4*)sred)[rg * 32 + l] = acc;
    __syncthreads();

    __shared__ float red[128];
    float pooled = 0.f;
    if (t < 128) {
        float sum = 0.f;
        #pragma unroll
        for (int k = 0; k < 8; k++) sum += sred[k * 128 + t];
        float cnt = (float)(e - s);
        pooled = sum / fmaxf(cnt, 1.f);
        red[t] = pooled;
    }
    __syncthreads();
    #pragma unroll
    for (int off = 64; off > 0; off >>= 1) {
        if (t < off) red[t] += red[t + off];
        __syncthreads();
    }
    float mu = red[0] * (1.f / 128.f);
    __syncthreads();
    if (t < 128) { float d = pooled - mu; red[t] = d * d; }
    __syncthreads();
    #pragma unroll
    for (int off = 64; off > 0; off >>= 1) {
        if (t < off) red[t] += red[t + off];
        __syncthreads();
    }
    if (t < 128) {
        float var = red[0] * (1.f / 128.f);
        float d = pooled - mu;
        out[g * D + t] = d * rsqrtf(var + 1e-5f) * gamma[t] + beta[t];
    }
}

// ---------------- launch: self-identifying input binding ----------------
extern "C" void kernel_launch(void* const* d_in, const int* in_sizes, int n_in,
                              void* d_out, int out_size) {
    // Rank inputs by size, stable on ties (preserves original relative order).
    int order[16];
    int m = (n_in < 16) ? n_in : 16;
    for (int i = 0; i < m; i++) order[i] = i;
    for (int i = 0; i < m; i++) {          // stable selection sort, descending size
        int best = i;
        for (int j = i + 1; j < m; j++)
            if (in_sizes[order[j]] > in_sizes[order[best]]) best = j;
        int t = order[i]; order[i] = order[best]; order[best] = t;
    }
    const int xi  = order[0];   // x           : N*D
    const int eii = order[1];   // edge_index  : 2E
    const int ewi = order[2];   // edge_weight : E
    const int bti = order[3];   // batch       : N
    const int wA  = order[4], wB = order[5];   // W pair
    const int bA  = order[6], bB = order[7];   // b pair
    const int lA  = order[8], lB = order[9];   // ln pair
    // Scheme detection: dict order puts x first; alphabetical puts W_neg first.
    const bool dict_order = (xi == 0);
    const int wPos = dict_order ? wA : wB;
    const int wNeg = dict_order ? wB : wA;
    const int bPos = dict_order ? bA : bB;
    const int bNeg = dict_order ? bB : bA;
    const int gI   = dict_order ? lA : lB;
    const int bI   = dict_order ? lB : lA;

    const float* x     = (const float*)d_in[xi];
    const void*  ei    = d_in[eii];            // int32 or int64, detected on device
    const float* ew    = (const float*)d_in[ewi];
    const void*  batch = d_in[bti];
    const float* W_pos = (const float*)d_in[wPos];
    const float* b_pos = (const float*)d_in[bPos];
    const float* W_neg = (const float*)d_in[wNeg];
    const float* b_neg = (const float*)d_in[bNeg];
    const float* gamma = (const float*)d_in[gI];
    const float* beta  = (const float*)d_in[bI];
    float* out = (float*)d_out;

    int N = in_sizes[xi] / D;
    int E = in_sizes[ewi];
    if (N > MAXN) N = MAXN;
    if (E > MAXE) E = MAXE;

    const int TB = 256;
    const int nb = (N + 255) / 256;
    detect_kernel<<<1, 32>>>((const int*)ei, in_sizes[eii]);
    init_kernel<<<(N + TB - 1) / TB, TB>>>(N);
    edge_deg_kernel<<<(E + TB - 1) / TB, TB>>>(ei, ew, E, N);
    dinv_kernel<<<(N + TB - 1) / TB, TB>>>(N);
    scanA_kernel<<<nb, 256>>>(N);
    scanB_kernel<<<1, 256>>>(nb);
    scanC_kernel<<<nb, 256>>>(N);
    edge_fill_kernel<<<(E + TB - 1) / TB, TB>>>(ei, ew, E, N);
    bounds_kernel<<<(N + TB - 1) / TB, TB>>>(batch, N);

    const int rowTiles = (N + 127) / 128;
    // layer 0: x -> h0 ; layer 1: h0 -> h1 ; layer 2: h1 -> h0
    const int src_sels[3] = { 0, 1, 2 };
    const int dst_sels[3] = { 0, 1, 0 };
    for (int l = 0; l < 3; l++) {
        gemm_dual_kernel<<<dim3(rowTiles, 2), 256>>>(x, src_sels[l],
                                                     W_pos + (size_t)l * D * D,
                                                     W_neg + (size_t)l * D * D, N);
        agg_kernel<<<N, 128>>>(b_pos + (size_t)l * D, b_neg + (size_t)l * D, dst_sels[l]);
    }
    pool_ln_kernel<<<NGRAPH, 256>>>(gamma, beta, out);
}